// round 15
// baseline (speedup 1.0000x reference)
#include <cuda_runtime.h>
#include <cuda_bf16.h>
#include <cstdint>

// Problem shape (fixed by dataset)
#define BB 64
#define LL 256
#define TT 1600
#define TC 32                       // time-chunk (= halo width)
#define SROW 33                     // smem row stride (floats), conflict-free
#define NBUF 4                      // pipeline depth
#define BUF_FLOATS (LL * SROW)      // 8448
#define SMEM_BYTES (NBUF * BUF_FLOATS * 4)   // 135,168 B
#define LN2 0.69314718055994531f
#define E_SENT (-(1 << 26))         // exponent sentinel (int)

__device__ float g_alpha_last[BB];
__device__ unsigned int g_done_ctr = 0;

__device__ __forceinline__ float f_lg2(float x) {
    float r; asm("lg2.approx.f32 %0, %1;" : "=f"(r) : "f"(x)); return r;
}
// 2^k as float, clamped: k>126 -> 2^126, k<-126 -> 0
__device__ __forceinline__ float pow2s(int k) {
    k = (k > 126) ? 126 : k;
    return (k < -126) ? 0.0f : __int_as_float((k + 127) << 23);
}

__device__ __forceinline__ void mbar_init(uint32_t a, uint32_t cnt) {
    asm volatile("mbarrier.init.shared.b64 [%0], %1;" :: "r"(a), "r"(cnt) : "memory");
}
__device__ __forceinline__ void mbar_arrive(uint32_t a) {
    asm volatile("mbarrier.arrive.shared.b64 _, [%0];" :: "r"(a) : "memory");
}
__device__ __forceinline__ void mbar_wait(uint32_t a, uint32_t phase) {
    asm volatile(
        "{\n\t.reg .pred P;\n\t"
        "WL_%=:\n\t"
        "mbarrier.try_wait.parity.acquire.cta.shared::cta.b64 P, [%0], %1, 0x989680;\n\t"
        "@P bra.uni WD_%=;\n\t"
        "bra.uni WL_%=;\n\t"
        "WD_%=:\n\t}"
        :: "r"(a), "r"(phase) : "memory");
}

extern __shared__ float sbuf[];   // NBUF buffers of [LL][SROW], probs + 1e-30

// ---------------------------------------------------------------------------
// Recursion kernel: one block per batch, 256 threads.
//   EARLY EXIT in t (chunks 0..ct) + DEAD-WARP EXIT in l (nact warps).
//   warps 4-7 (convert): LDG.128 (16/warp, compile-time unrolled, MLP~16)
//     -> +1e-30 -> STS (raw, for recursion) AND lg2*ln2 -> STG (the output
//     matrix for chunks 0..ct — k_elem2 covers the complement).
//   warps 0-3 (recursion): linear-domain block-FP alpha (a*2^E), 3 slots/
//     thread, renorm every 16 steps, halo every 32.
// ---------------------------------------------------------------------------
__global__ void __launch_bounds__(256, 1)
k_rec(const float* __restrict__ probs,
      const int* __restrict__ text_lengths,
      const int* __restrict__ mel_lengths,
      float* __restrict__ out)
{
    __shared__ float hA[2][4][32];      // halo exchange: mantissas
    __shared__ int   hE[2][4][32];      // halo exchange: exponents
    __shared__ __align__(8) unsigned long long mbar_store[2 * NBUF];

    const int b    = blockIdx.x;
    const int tid  = threadIdx.x;
    const int warp = tid >> 5;
    const int lane = tid & 31;

    const int tgt_t = __ldg(mel_lengths  + b) - 1;
    const int tgt_l = __ldg(text_lengths + b) - 1;
    const int ct    = tgt_t >> 5;               // last needed chunk
    const int nact  = (tgt_l >> 6) + 1;         // active recursion warps (1..4)

    const float* pbase = probs + (size_t)b * LL * TT;
    float*       obase = out + 1 + (size_t)b * LL * TT;

    const uint32_t mb = (uint32_t)__cvta_generic_to_shared(mbar_store);
#define FULL_A(s)  (mb + (uint32_t)(s) * 8u)
#define EMPTY_A(s) (mb + 32u + (uint32_t)(s) * 8u)

    if (tid == 0) {
#pragma unroll
        for (int s = 0; s < NBUF; ++s) {
            mbar_init(FULL_A(s), 4);               // one per convert warp
            mbar_init(EMPTY_A(s), (uint32_t)nact); // one per ACTIVE rec warp
        }
    }
    __syncthreads();

    if (warp >= 4) {
        // ====== convert / producer: stage (raw) + write log output ======
        const int wtid = tid - 128;     // 0..127
        for (int c = 0; c <= ct; ++c) {
            const int s = c & 3, u = c >> 2;
            mbar_wait(EMPTY_A(s), (u & 1) ^ 1);
            float* buf = sbuf + s * BUF_FLOATS;
            const float* gsrc = pbase + c * TC;
            float*       gdst = obase + c * TC;
#pragma unroll
            for (int k = 0; k < 16; ++k) {
                const int i   = wtid + k * 128;    // 0..2047
                const int row = i >> 3;
                const int c4  = (i & 7) * 4;
                const float4 v = *reinterpret_cast<const float4*>(
                                     gsrc + (size_t)row * TT + c4);
                const float s0 = v.x + 1e-30f, s1 = v.y + 1e-30f;
                const float s2 = v.z + 1e-30f, s3 = v.w + 1e-30f;
                float* sp = buf + row * SROW + c4;
                sp[0] = s0; sp[1] = s1; sp[2] = s2; sp[3] = s3;
                float* gp = gdst + (size_t)row * TT + c4;  // 4B-aligned
                gp[0] = f_lg2(s0) * LN2; gp[1] = f_lg2(s1) * LN2;
                gp[2] = f_lg2(s2) * LN2; gp[3] = f_lg2(s3) * LN2;
            }
            if (lane == 0) mbar_arrive(FULL_A(s));
        }
    } else if (warp < nact) {
        // ======================= recursion / consumer ======================
        const int Wb = 64 * warp - 32;
        const int r0 = Wb + 3 * lane, r1 = r0 + 1, r2 = r0 + 2;
        const int cr0 = ((r0 >= 0) ? r0 : 0) * SROW;   // invalid slots keep a=0
        const int cr1 = ((r1 >= 0) ? r1 : 0) * SROW;
        const int cr2 = ((r2 >= 0) ? r2 : 0) * SROW;
        const unsigned bar_n = (unsigned)(nact << 5);  // halo barrier threads

        const int wt   = tgt_l >> 6;
        const int slot = (tgt_l & 63) + 32;
        const bool mine = (warp == wt) && (lane == slot / 3);
        const int  msel = slot - 3 * (slot / 3);

        float a0 = 0.f, a1 = 0.f, a2 = 0.f;
        int   e0 = E_SENT, e1 = E_SENT, e2 = E_SENT;
        float f0 = 0.f, f1 = 0.f, f2 = 0.f;

#define SNAPVAL(AV, EV) ((AV) == 0.0f ? -1e30f : (f_lg2(AV) + (float)(EV)) * LN2)

#define STEP(BUFC, J, T)                                                  \
        {                                                                 \
            float p0 = (BUFC)[cr0 + (J)];                                 \
            float p1 = (BUFC)[cr1 + (J)];                                 \
            float p2 = (BUFC)[cr2 + (J)];                                 \
            float sh = __shfl_up_sync(0xffffffffu, a2, 1);                \
            float t0 = fmaf(sh, f0, a0);     /* lane0: f0==0 */           \
            float t1 = fmaf(a0, f1, a1);                                  \
            float t2 = fmaf(a1, f2, a2);                                  \
            a0 = t0 * p0; a1 = t1 * p1; a2 = t2 * p2;                     \
            if (mine && (T) == tgt_t) {                                   \
                float av = (msel == 0) ? a0 : ((msel == 1) ? a1 : a2);    \
                int   ev = (msel == 0) ? e0 : ((msel == 1) ? e1 : e2);    \
                g_alpha_last[b] = SNAPVAL(av, ev);                        \
            }                                                             \
        }

#define RENORM()                                                          \
        {                                                                 \
            int bi, ex;                                                   \
            bi = __float_as_int(a0); ex = (bi >> 23) & 255;               \
            bool R0 = (ex != 0);                                          \
            if (R0) { e0 += ex - 127;                                     \
                      a0 = __int_as_float((bi & 0x807FFFFF) | 0x3F800000);}\
            else    { a0 = 0.f; e0 = E_SENT; }                            \
            bi = __float_as_int(a1); ex = (bi >> 23) & 255;               \
            bool R1 = (ex != 0);                                          \
            if (R1) { e1 += ex - 127;                                     \
                      a1 = __int_as_float((bi & 0x807FFFFF) | 0x3F800000);}\
            else    { a1 = 0.f; e1 = E_SENT; }                            \
            bi = __float_as_int(a2); ex = (bi >> 23) & 255;               \
            bool R2 = (ex != 0);                                          \
            if (R2) { e2 += ex - 127;                                     \
                      a2 = __int_as_float((bi & 0x807FFFFF) | 0x3F800000);}\
            else    { a2 = 0.f; e2 = E_SENT; }                            \
            int lv = R2 ? e2 : (R1 ? e1 : (R0 ? e0 : E_SENT));            \
            int lf = (int)(R0 | R1 | R2);                                 \
            _Pragma("unroll")                                             \
            for (int d = 1; d < 8; d <<= 1) {                             \
                int ov = __shfl_up_sync(0xffffffffu, lv, d);              \
                int of = __shfl_up_sync(0xffffffffu, lf, d);              \
                if (lane >= d && !lf) { lv = ov; lf = of; }               \
            }                                                             \
            int Lin = __shfl_up_sync(0xffffffffu, lv, 1);                 \
            if (lane == 0) Lin = E_SENT;                                  \
            int pl = __shfl_up_sync(0xffffffffu, e2, 1);                  \
            if (lane == 0) pl = E_SENT;                                   \
            int P0 = R0 ? ((e0 > pl) ? e0 : pl) : Lin;                    \
            int L1 = R0 ? e0 : Lin;                                       \
            int P1 = R1 ? ((e1 > e0) ? e1 : e0) : L1;                     \
            int L2 = R1 ? e1 : L1;                                        \
            int P2 = R2 ? ((e2 > e1) ? e2 : e1) : L2;                     \
            a0 *= pow2s(e0 - P0);                                         \
            a1 *= pow2s(e1 - P1);                                         \
            a2 *= pow2s(e2 - P2);                                         \
            int PL = __shfl_up_sync(0xffffffffu, P2, 1);                  \
            if (lane == 0) PL = E_SENT;                                   \
            f0 = pow2s(PL - P0);                                          \
            if (lane == 0) f0 = 0.0f;   /* degradation front */           \
            f1 = pow2s(P0 - P1);                                          \
            f2 = pow2s(P1 - P2);                                          \
            e0 = P0; e1 = P1; e2 = P2;                                    \
        }

#define HALO(C)                                                           \
        {                                                                 \
            const int s0 = 3 * lane;                                      \
            float* ha = &hA[(C) & 1][warp][0];                            \
            int*   he = &hE[(C) & 1][warp][0];                            \
            if (s0     >= 64) { ha[s0 - 64] = a0; he[s0 - 64] = e0; }     \
            if (s0 + 1 >= 64) { ha[s0 - 63] = a1; he[s0 - 63] = e1; }     \
            if (s0 + 2 >= 64) { ha[s0 - 62] = a2; he[s0 - 62] = e2; }     \
            asm volatile("bar.sync 1, %0;" :: "r"(bar_n) : "memory");     \
            if (warp > 0) {                                               \
                const float* ra = &hA[(C) & 1][warp - 1][0];              \
                const int*   re = &hE[(C) & 1][warp - 1][0];              \
                if (s0     < 32) { a0 = ra[s0];     e0 = re[s0];     }    \
                if (s0 + 1 < 32) { a1 = ra[s0 + 1]; e1 = re[s0 + 1]; }    \
                if (s0 + 2 < 32) { a2 = ra[s0 + 2]; e2 = re[s0 + 2]; }    \
            }                                                             \
        }

        // ---- chunk 0 (t=0 is init, steps t=1..31) ----
        mbar_wait(FULL_A(0), 0);
        {
            const float* bufc = sbuf;
            if (warp == 0 && lane == 10) { a2 = bufc[0]; e2 = 0; }  // pre-floored
            if (tgt_t == 0 && mine) {
                float av = (msel == 0) ? a0 : ((msel == 1) ? a1 : a2);
                int   ev = (msel == 0) ? e0 : ((msel == 1) ? e1 : e2);
                g_alpha_last[b] = SNAPVAL(av, ev);
            }
            RENORM()
#pragma unroll
            for (int j = 1; j < 16; ++j) STEP(bufc, j, j)
            RENORM()
#pragma unroll
            for (int j = 16; j < 32; ++j) STEP(bufc, j, j)
        }
        if (lane == 0) mbar_arrive(EMPTY_A(0));
        HALO(0)

        // ---- chunks 1..ct ----
        for (int c = 1; c <= ct; ++c) {
            const int s = c & 3, u = c >> 2;
            mbar_wait(FULL_A(s), u & 1);
            const float* bufc = sbuf + s * BUF_FLOATS;
            const int tbase = c * TC;
            RENORM()
#pragma unroll
            for (int j = 0; j < 16; ++j) STEP(bufc, j, tbase + j)
            RENORM()
#pragma unroll
            for (int j = 16; j < 32; ++j) STEP(bufc, j, tbase + j)
            if (lane == 0) mbar_arrive(EMPTY_A(s));
            HALO(c)
        }
    }

    __syncthreads();

    // last block to finish computes loss = -mean(alpha_last)
    if (tid == 0) {
        __threadfence();
        unsigned old = atomicAdd(&g_done_ctr, 1u);
        if (old == BB - 1) {
            g_done_ctr = 0;                          // reset for graph replay
            __threadfence();
            float s = 0.0f;
#pragma unroll
            for (int i = 0; i < BB; ++i) s += g_alpha_last[i];
            out[0] = -s * (1.0f / BB);
        }
    }
}

// ---------------------------------------------------------------------------
// Complement elementwise kernel (forked stream): writes log matrix for
// chunks > ct_b only (k_rec's convert warps cover chunks 0..ct_b).
// Grid: 64 batches x 25 double-chunks (64 t each). 256 threads.
// ---------------------------------------------------------------------------
__global__ void __launch_bounds__(256)
k_elem2(const float* __restrict__ probs,
        const int* __restrict__ mel_lengths,
        float* __restrict__ out)
{
    const int b  = blockIdx.x / 25;
    const int cc = blockIdx.x % 25;
    const int ct = (__ldg(mel_lengths + b) - 1) >> 5;
    const int tid = threadIdx.x;

    const size_t base = (size_t)b * LL * TT;

#pragma unroll
    for (int h = 0; h < 2; ++h) {
        const int chunk = 2 * cc + h;
        if (chunk > ct) {
            const float* gsrc = probs + base + chunk * TC;
            float*       gdst = out + 1 + base + chunk * TC;
#pragma unroll
            for (int k = 0; k < 8; ++k) {
                const int i   = tid + k * 256;     // 0..2047
                const int row = i >> 3;
                const int c4  = (i & 7) * 4;
                const float4 v = *reinterpret_cast<const float4*>(
                                     gsrc + (size_t)row * TT + c4);
                float* gp = gdst + (size_t)row * TT + c4;  // 4B-aligned
                gp[0] = __logf(v.x + 1e-30f);
                gp[1] = __logf(v.y + 1e-30f);
                gp[2] = __logf(v.z + 1e-30f);
                gp[3] = __logf(v.w + 1e-30f);
            }
        }
    }
}

// ---------------------------------------------------------------------------
extern "C" void kernel_launch(void* const* d_in, const int* in_sizes, int n_in,
                              void* d_out, int out_size)
{
    const float* probs        = (const float*)d_in[0];
    // d_in[1] = melspec (unused by the computation)
    const int*   text_lengths = (const int*)d_in[2];
    const int*   mel_lengths  = (const int*)d_in[3];

    float* out = (float*)d_out;   // out[0] = loss, out[1..] = log matrix

    static cudaStream_t s2 = nullptr;
    static cudaEvent_t  evF = nullptr, evJ = nullptr;
    if (s2 == nullptr) {
        cudaStreamCreateWithFlags(&s2, cudaStreamNonBlocking);
        cudaEventCreateWithFlags(&evF, cudaEventDisableTiming);
        cudaEventCreateWithFlags(&evJ, cudaEventDisableTiming);
        cudaFuncSetAttribute(k_rec, cudaFuncAttributeMaxDynamicSharedMemorySize,
                             SMEM_BYTES);
    }

    // fork: complement elementwise on s2, recursion (+ head output) on main
    cudaEventRecord(evF, 0);
    cudaStreamWaitEvent(s2, evF, 0);
    k_elem2<<<BB * 25, 256, 0, s2>>>(probs, mel_lengths, out);
    cudaEventRecord(evJ, s2);

    k_rec<<<BB, 256, SMEM_BYTES, 0>>>(probs, text_lengths, mel_lengths, out);

    // join
    cudaStreamWaitEvent(0, evJ, 0);
    (void)in_sizes; (void)n_in; (void)out_size;
}

// round 16
// speedup vs baseline: 1.0712x; 1.0712x over previous
#include <cuda_runtime.h>
#include <cuda_bf16.h>
#include <cstdint>

// Problem shape (fixed by dataset)
#define BB 64
#define LL 256
#define TT 1600
#define TC 32                       // time-chunk (= halo width)
#define SROW 33                     // smem row stride (floats), conflict-free
#define NBUF 4                      // pipeline depth
#define BUF_FLOATS (LL * SROW)      // 8448
#define SMEM_BYTES (NBUF * BUF_FLOATS * 4)   // 135,168 B
#define LN2 0.69314718055994531f
#define E_SENT (-(1 << 26))         // exponent sentinel (int)

__device__ float g_alpha_last[BB];
__device__ unsigned int g_done_ctr = 0;

__device__ __forceinline__ float f_lg2(float x) {
    float r; asm("lg2.approx.f32 %0, %1;" : "=f"(r) : "f"(x)); return r;
}
// 2^k as float, clamped: k>126 -> 2^126, k<-126 -> 0
__device__ __forceinline__ float pow2s(int k) {
    k = (k > 126) ? 126 : k;
    return (k < -126) ? 0.0f : __int_as_float((k + 127) << 23);
}

__device__ __forceinline__ void mbar_init(uint32_t a, uint32_t cnt) {
    asm volatile("mbarrier.init.shared.b64 [%0], %1;" :: "r"(a), "r"(cnt) : "memory");
}
__device__ __forceinline__ void mbar_arrive(uint32_t a) {
    asm volatile("mbarrier.arrive.shared.b64 _, [%0];" :: "r"(a) : "memory");
}
__device__ __forceinline__ void mbar_wait(uint32_t a, uint32_t phase) {
    asm volatile(
        "{\n\t.reg .pred P;\n\t"
        "WL_%=:\n\t"
        "mbarrier.try_wait.parity.acquire.cta.shared::cta.b64 P, [%0], %1, 0x989680;\n\t"
        "@P bra.uni WD_%=;\n\t"
        "bra.uni WL_%=;\n\t"
        "WD_%=:\n\t}"
        :: "r"(a), "r"(phase) : "memory");
}

extern __shared__ float sbuf[];   // NBUF buffers of [LL][SROW], probs + 1e-30

// ---------------------------------------------------------------------------
// Recursion kernel: one block per batch, 384 threads (12 warps).
//   warps 0-3  (recursion): R14 layout — linear-domain block-FP alpha,
//     3 slots/thread, renorm/16, halo/32; dead-warp exit (nact).
//   warps 4-7  (convert): LDG.128 (compile-time unrolled, MLP~16) -> +1e-30
//     -> STS raw. NO gmem stores (R15 regression: stores paced the producer).
//   warps 8-11 (writer): second FULL consumer — LDS raw from ring, lg2*ln2,
//     STG the output matrix for chunks 0..ct. Hidden in rec-warp stall slots.
//   EMPTY count = nact + 4 (rec + writer). Early exit in t (chunks 0..ct).
// ---------------------------------------------------------------------------
__global__ void __launch_bounds__(384, 1)
k_rec(const float* __restrict__ probs,
      const int* __restrict__ text_lengths,
      const int* __restrict__ mel_lengths,
      float* __restrict__ out)
{
    __shared__ float hA[2][4][32];      // halo exchange: mantissas
    __shared__ int   hE[2][4][32];      // halo exchange: exponents
    __shared__ __align__(8) unsigned long long mbar_store[2 * NBUF];

    const int b    = blockIdx.x;
    const int tid  = threadIdx.x;
    const int warp = tid >> 5;
    const int lane = tid & 31;

    const int tgt_t = __ldg(mel_lengths  + b) - 1;
    const int tgt_l = __ldg(text_lengths + b) - 1;
    const int ct    = tgt_t >> 5;               // last needed chunk
    const int nact  = (tgt_l >> 6) + 1;         // active recursion warps (1..4)

    const float* pbase = probs + (size_t)b * LL * TT;
    float*       obase = out + 1 + (size_t)b * LL * TT;

    const uint32_t mb = (uint32_t)__cvta_generic_to_shared(mbar_store);
#define FULL_A(s)  (mb + (uint32_t)(s) * 8u)
#define EMPTY_A(s) (mb + 32u + (uint32_t)(s) * 8u)

    if (tid == 0) {
#pragma unroll
        for (int s = 0; s < NBUF; ++s) {
            mbar_init(FULL_A(s), 4);                   // convert arrivals
            mbar_init(EMPTY_A(s), (uint32_t)nact + 4); // rec + writer arrivals
        }
    }
    __syncthreads();

    if (warp >= 8) {
        // ====== writer: FULL consumer -> log output for chunks 0..ct ======
        const int wrow0 = 64 * (warp - 8);   // rows [wrow0, wrow0+64)
        for (int c = 0; c <= ct; ++c) {
            const int s = c & 3, u = c >> 2;
            mbar_wait(FULL_A(s), u & 1);
            const float* buf = sbuf + s * BUF_FLOATS;
            float* gdst = obase + c * TC;
#pragma unroll 16
            for (int r = 0; r < 64; ++r) {
                const int row = wrow0 + r;
                float v = buf[row * SROW + lane];          // conflict-free
                gdst[(size_t)row * TT + lane] = f_lg2(v) * LN2;  // coalesced
            }
            if (lane == 0) mbar_arrive(EMPTY_A(s));
        }
    } else if (warp >= 4) {
        // ============== convert / producer (copy + 1e-30 floor) ============
        const int wtid = tid - 128;     // 0..127
        for (int c = 0; c <= ct; ++c) {
            const int s = c & 3, u = c >> 2;
            mbar_wait(EMPTY_A(s), (u & 1) ^ 1);
            float* buf = sbuf + s * BUF_FLOATS;
            const float* gsrc = pbase + c * TC;
#pragma unroll
            for (int k = 0; k < 16; ++k) {
                const int i   = wtid + k * 128;    // 0..2047
                const int row = i >> 3;
                const int c4  = (i & 7) * 4;
                const float4 v = *reinterpret_cast<const float4*>(
                                     gsrc + (size_t)row * TT + c4);
                float* sp = buf + row * SROW + c4;
                sp[0] = v.x + 1e-30f; sp[1] = v.y + 1e-30f;
                sp[2] = v.z + 1e-30f; sp[3] = v.w + 1e-30f;
            }
            if (lane == 0) mbar_arrive(FULL_A(s));
        }
    } else if (warp < nact) {
        // ======================= recursion / consumer ======================
        const int Wb = 64 * warp - 32;
        const int r0 = Wb + 3 * lane, r1 = r0 + 1, r2 = r0 + 2;
        const int cr0 = ((r0 >= 0) ? r0 : 0) * SROW;   // invalid slots keep a=0
        const int cr1 = ((r1 >= 0) ? r1 : 0) * SROW;
        const int cr2 = ((r2 >= 0) ? r2 : 0) * SROW;
        const unsigned bar_n = (unsigned)(nact << 5);  // halo barrier threads

        const int wt   = tgt_l >> 6;
        const int slot = (tgt_l & 63) + 32;
        const bool mine = (warp == wt) && (lane == slot / 3);
        const int  msel = slot - 3 * (slot / 3);

        float a0 = 0.f, a1 = 0.f, a2 = 0.f;
        int   e0 = E_SENT, e1 = E_SENT, e2 = E_SENT;
        float f0 = 0.f, f1 = 0.f, f2 = 0.f;

#define SNAPVAL(AV, EV) ((AV) == 0.0f ? -1e30f : (f_lg2(AV) + (float)(EV)) * LN2)

#define STEP(BUFC, J, T)                                                  \
        {                                                                 \
            float p0 = (BUFC)[cr0 + (J)];                                 \
            float p1 = (BUFC)[cr1 + (J)];                                 \
            float p2 = (BUFC)[cr2 + (J)];                                 \
            float sh = __shfl_up_sync(0xffffffffu, a2, 1);                \
            float t0 = fmaf(sh, f0, a0);     /* lane0: f0==0 */           \
            float t1 = fmaf(a0, f1, a1);                                  \
            float t2 = fmaf(a1, f2, a2);                                  \
            a0 = t0 * p0; a1 = t1 * p1; a2 = t2 * p2;                     \
            if (mine && (T) == tgt_t) {                                   \
                float av = (msel == 0) ? a0 : ((msel == 1) ? a1 : a2);    \
                int   ev = (msel == 0) ? e0 : ((msel == 1) ? e1 : e2);    \
                g_alpha_last[b] = SNAPVAL(av, ev);                        \
            }                                                             \
        }

#define RENORM()                                                          \
        {                                                                 \
            int bi, ex;                                                   \
            bi = __float_as_int(a0); ex = (bi >> 23) & 255;               \
            bool R0 = (ex != 0);                                          \
            if (R0) { e0 += ex - 127;                                     \
                      a0 = __int_as_float((bi & 0x807FFFFF) | 0x3F800000);}\
            else    { a0 = 0.f; e0 = E_SENT; }                            \
            bi = __float_as_int(a1); ex = (bi >> 23) & 255;               \
            bool R1 = (ex != 0);                                          \
            if (R1) { e1 += ex - 127;                                     \
                      a1 = __int_as_float((bi & 0x807FFFFF) | 0x3F800000);}\
            else    { a1 = 0.f; e1 = E_SENT; }                            \
            bi = __float_as_int(a2); ex = (bi >> 23) & 255;               \
            bool R2 = (ex != 0);                                          \
            if (R2) { e2 += ex - 127;                                     \
                      a2 = __int_as_float((bi & 0x807FFFFF) | 0x3F800000);}\
            else    { a2 = 0.f; e2 = E_SENT; }                            \
            int lv = R2 ? e2 : (R1 ? e1 : (R0 ? e0 : E_SENT));            \
            int lf = (int)(R0 | R1 | R2);                                 \
            _Pragma("unroll")                                             \
            for (int d = 1; d < 8; d <<= 1) {                             \
                int ov = __shfl_up_sync(0xffffffffu, lv, d);              \
                int of = __shfl_up_sync(0xffffffffu, lf, d);              \
                if (lane >= d && !lf) { lv = ov; lf = of; }               \
            }                                                             \
            int Lin = __shfl_up_sync(0xffffffffu, lv, 1);                 \
            if (lane == 0) Lin = E_SENT;                                  \
            int pl = __shfl_up_sync(0xffffffffu, e2, 1);                  \
            if (lane == 0) pl = E_SENT;                                   \
            int P0 = R0 ? ((e0 > pl) ? e0 : pl) : Lin;                    \
            int L1 = R0 ? e0 : Lin;                                       \
            int P1 = R1 ? ((e1 > e0) ? e1 : e0) : L1;                     \
            int L2 = R1 ? e1 : L1;                                        \
            int P2 = R2 ? ((e2 > e1) ? e2 : e1) : L2;                     \
            a0 *= pow2s(e0 - P0);                                         \
            a1 *= pow2s(e1 - P1);                                         \
            a2 *= pow2s(e2 - P2);                                         \
            int PL = __shfl_up_sync(0xffffffffu, P2, 1);                  \
            if (lane == 0) PL = E_SENT;                                   \
            f0 = pow2s(PL - P0);                                          \
            if (lane == 0) f0 = 0.0f;   /* degradation front */           \
            f1 = pow2s(P0 - P1);                                          \
            f2 = pow2s(P1 - P2);                                          \
            e0 = P0; e1 = P1; e2 = P2;                                    \
        }

#define HALO(C)                                                           \
        {                                                                 \
            const int s0 = 3 * lane;                                      \
            float* ha = &hA[(C) & 1][warp][0];                            \
            int*   he = &hE[(C) & 1][warp][0];                            \
            if (s0     >= 64) { ha[s0 - 64] = a0; he[s0 - 64] = e0; }     \
            if (s0 + 1 >= 64) { ha[s0 - 63] = a1; he[s0 - 63] = e1; }     \
            if (s0 + 2 >= 64) { ha[s0 - 62] = a2; he[s0 - 62] = e2; }     \
            asm volatile("bar.sync 1, %0;" :: "r"(bar_n) : "memory");     \
            if (warp > 0) {                                               \
                const float* ra = &hA[(C) & 1][warp - 1][0];              \
                const int*   re = &hE[(C) & 1][warp - 1][0];              \
                if (s0     < 32) { a0 = ra[s0];     e0 = re[s0];     }    \
                if (s0 + 1 < 32) { a1 = ra[s0 + 1]; e1 = re[s0 + 1]; }    \
                if (s0 + 2 < 32) { a2 = ra[s0 + 2]; e2 = re[s0 + 2]; }    \
            }                                                             \
        }

        // ---- chunk 0 (t=0 is init, steps t=1..31) ----
        mbar_wait(FULL_A(0), 0);
        {
            const float* bufc = sbuf;
            if (warp == 0 && lane == 10) { a2 = bufc[0]; e2 = 0; }  // pre-floored
            if (tgt_t == 0 && mine) {
                float av = (msel == 0) ? a0 : ((msel == 1) ? a1 : a2);
                int   ev = (msel == 0) ? e0 : ((msel == 1) ? e1 : e2);
                g_alpha_last[b] = SNAPVAL(av, ev);
            }
            RENORM()
#pragma unroll
            for (int j = 1; j < 16; ++j) STEP(bufc, j, j)
            RENORM()
#pragma unroll
            for (int j = 16; j < 32; ++j) STEP(bufc, j, j)
        }
        if (lane == 0) mbar_arrive(EMPTY_A(0));
        HALO(0)

        // ---- chunks 1..ct ----
        for (int c = 1; c <= ct; ++c) {
            const int s = c & 3, u = c >> 2;
            mbar_wait(FULL_A(s), u & 1);
            const float* bufc = sbuf + s * BUF_FLOATS;
            const int tbase = c * TC;
            RENORM()
#pragma unroll
            for (int j = 0; j < 16; ++j) STEP(bufc, j, tbase + j)
            RENORM()
#pragma unroll
            for (int j = 16; j < 32; ++j) STEP(bufc, j, tbase + j)
            if (lane == 0) mbar_arrive(EMPTY_A(s));
            HALO(c)
        }
    }

    __syncthreads();

    // last block to finish computes loss = -mean(alpha_last)
    if (tid == 0) {
        __threadfence();
        unsigned old = atomicAdd(&g_done_ctr, 1u);
        if (old == BB - 1) {
            g_done_ctr = 0;                          // reset for graph replay
            __threadfence();
            float s = 0.0f;
#pragma unroll
            for (int i = 0; i < BB; ++i) s += g_alpha_last[i];
            out[0] = -s * (1.0f / BB);
        }
    }
}

// ---------------------------------------------------------------------------
// Complement elementwise kernel (forked stream): writes log matrix for
// chunks > ct_b only (k_rec covers chunks 0..ct_b).
// Grid: 64 batches x 25 double-chunks (64 t each). 256 threads.
// ---------------------------------------------------------------------------
__global__ void __launch_bounds__(256)
k_elem2(const float* __restrict__ probs,
        const int* __restrict__ mel_lengths,
        float* __restrict__ out)
{
    const int b  = blockIdx.x / 25;
    const int cc = blockIdx.x % 25;
    const int ct = (__ldg(mel_lengths + b) - 1) >> 5;
    const int tid = threadIdx.x;

    const size_t base = (size_t)b * LL * TT;

#pragma unroll
    for (int h = 0; h < 2; ++h) {
        const int chunk = 2 * cc + h;
        if (chunk > ct) {
            const float* gsrc = probs + base + chunk * TC;
            float*       gdst = out + 1 + base + chunk * TC;
#pragma unroll
            for (int k = 0; k < 8; ++k) {
                const int i   = tid + k * 256;     // 0..2047
                const int row = i >> 3;
                const int c4  = (i & 7) * 4;
                const float4 v = *reinterpret_cast<const float4*>(
                                     gsrc + (size_t)row * TT + c4);
                float* gp = gdst + (size_t)row * TT + c4;  // 4B-aligned
                gp[0] = __logf(v.x + 1e-30f);
                gp[1] = __logf(v.y + 1e-30f);
                gp[2] = __logf(v.z + 1e-30f);
                gp[3] = __logf(v.w + 1e-30f);
            }
        }
    }
}

// ---------------------------------------------------------------------------
extern "C" void kernel_launch(void* const* d_in, const int* in_sizes, int n_in,
                              void* d_out, int out_size)
{
    const float* probs        = (const float*)d_in[0];
    // d_in[1] = melspec (unused by the computation)
    const int*   text_lengths = (const int*)d_in[2];
    const int*   mel_lengths  = (const int*)d_in[3];

    float* out = (float*)d_out;   // out[0] = loss, out[1..] = log matrix

    static cudaStream_t s2 = nullptr;
    static cudaEvent_t  evF = nullptr, evJ = nullptr;
    if (s2 == nullptr) {
        cudaStreamCreateWithFlags(&s2, cudaStreamNonBlocking);
        cudaEventCreateWithFlags(&evF, cudaEventDisableTiming);
        cudaEventCreateWithFlags(&evJ, cudaEventDisableTiming);
        cudaFuncSetAttribute(k_rec, cudaFuncAttributeMaxDynamicSharedMemorySize,
                             SMEM_BYTES);
    }

    // fork: complement elementwise on s2, recursion (+ head output) on main
    cudaEventRecord(evF, 0);
    cudaStreamWaitEvent(s2, evF, 0);
    k_elem2<<<BB * 25, 256, 0, s2>>>(probs, mel_lengths, out);
    cudaEventRecord(evJ, s2);

    k_rec<<<BB, 384, SMEM_BYTES, 0>>>(probs, text_lengths, mel_lengths, out);

    // join
    cudaStreamWaitEvent(0, evJ, 0);
    (void)in_sizes; (void)n_in; (void)out_size;
}

// round 17
// speedup vs baseline: 1.3318x; 1.2432x over previous
#include <cuda_runtime.h>
#include <cuda_bf16.h>
#include <cstdint>

// Problem shape (fixed by dataset)
#define BB 64
#define LL 256
#define TT 1600
#define TC 32                       // time-chunk (= halo width)
#define SROW 33                     // smem row stride (floats), conflict-free
#define NBUF 4                      // pipeline depth
#define NCH 50                      // TT / TC
#define BUF_FLOATS (LL * SROW)      // 8448
#define SMEM_BYTES (NBUF * BUF_FLOATS * 4)   // 135,168 B
#define LN2 0.69314718055994531f
#define E_SENT (-(1 << 26))         // exponent sentinel (int)

__device__ float g_alpha_last[BB];
__device__ unsigned int g_done_ctr = 0;

__device__ __forceinline__ float f_lg2(float x) {
    float r; asm("lg2.approx.f32 %0, %1;" : "=f"(r) : "f"(x)); return r;
}
// 2^k as float, clamped: k>126 -> 2^126, k<-126 -> 0
__device__ __forceinline__ float pow2s(int k) {
    k = (k > 126) ? 126 : k;
    return (k < -126) ? 0.0f : __int_as_float((k + 127) << 23);
}

__device__ __forceinline__ void mbar_init(uint32_t a, uint32_t cnt) {
    asm volatile("mbarrier.init.shared.b64 [%0], %1;" :: "r"(a), "r"(cnt) : "memory");
}
__device__ __forceinline__ void mbar_arrive(uint32_t a) {
    asm volatile("mbarrier.arrive.shared.b64 _, [%0];" :: "r"(a) : "memory");
}
__device__ __forceinline__ void mbar_wait(uint32_t a, uint32_t phase) {
    asm volatile(
        "{\n\t.reg .pred P;\n\t"
        "WL_%=:\n\t"
        "mbarrier.try_wait.parity.acquire.cta.shared::cta.b64 P, [%0], %1, 0x989680;\n\t"
        "@P bra.uni WD_%=;\n\t"
        "bra.uni WL_%=;\n\t"
        "WD_%=:\n\t}"
        :: "r"(a), "r"(phase) : "memory");
}

extern __shared__ float sbuf[];   // NBUF buffers of [LL][SROW], probs + 1e-30

// ---------------------------------------------------------------------------
// SINGLE kernel: one block per batch, 384 threads (12 warps). Each block
// produces its batch's ENTIRE output: loss contribution + full log matrix.
//   warps 0-3  (recursion): linear-domain block-FP alpha (a*2^E), 3 slots/
//     thread, renorm/16, halo/32; dead-warp exit (nact).
//   warps 4-7  (convert): LDG.128 (unrolled, MLP~16) -> +1e-30 -> STS raw.
//   warps 8-11 (writer): FULL consumer — LDS raw, lg2*ln2, STG output for
//     chunks 0..ct.
//   POST-PHASE (all warps, as they drain): elementwise log output for
//     chunks ct+1..49. Dead rec warps start immediately -> free overlap.
//   No second kernel, no stream fork (R9-R16 fork never actually overlapped:
//   total-k_rec was a constant ~34us independent of k_elem work).
// ---------------------------------------------------------------------------
__global__ void __launch_bounds__(384, 1)
k_rec(const float* __restrict__ probs,
      const int* __restrict__ text_lengths,
      const int* __restrict__ mel_lengths,
      float* __restrict__ out)
{
    __shared__ float hA[2][4][32];      // halo exchange: mantissas
    __shared__ int   hE[2][4][32];      // halo exchange: exponents
    __shared__ __align__(8) unsigned long long mbar_store[2 * NBUF];

    const int b    = blockIdx.x;
    const int tid  = threadIdx.x;
    const int warp = tid >> 5;
    const int lane = tid & 31;

    const int tgt_t = __ldg(mel_lengths  + b) - 1;
    const int tgt_l = __ldg(text_lengths + b) - 1;
    const int ct    = tgt_t >> 5;               // last recursion chunk
    const int nact  = (tgt_l >> 6) + 1;         // active recursion warps (1..4)

    const float* pbase = probs + (size_t)b * LL * TT;
    float*       obase = out + 1 + (size_t)b * LL * TT;

    const uint32_t mb = (uint32_t)__cvta_generic_to_shared(mbar_store);
#define FULL_A(s)  (mb + (uint32_t)(s) * 8u)
#define EMPTY_A(s) (mb + 32u + (uint32_t)(s) * 8u)

    if (tid == 0) {
#pragma unroll
        for (int s = 0; s < NBUF; ++s) {
            mbar_init(FULL_A(s), 4);                   // convert arrivals
            mbar_init(EMPTY_A(s), (uint32_t)nact + 4); // rec + writer arrivals
        }
    }
    __syncthreads();

    if (warp >= 8) {
        // ====== writer: FULL consumer -> log output for chunks 0..ct ======
        const int wrow0 = 64 * (warp - 8);   // rows [wrow0, wrow0+64)
        for (int c = 0; c <= ct; ++c) {
            const int s = c & 3, u = c >> 2;
            mbar_wait(FULL_A(s), u & 1);
            const float* buf = sbuf + s * BUF_FLOATS;
            float* gdst = obase + c * TC;
#pragma unroll 16
            for (int r = 0; r < 64; ++r) {
                const int row = wrow0 + r;
                float v = buf[row * SROW + lane];              // conflict-free
                gdst[(size_t)row * TT + lane] = f_lg2(v) * LN2; // coalesced
            }
            if (lane == 0) mbar_arrive(EMPTY_A(s));
        }
    } else if (warp >= 4) {
        // ============== convert / producer (copy + 1e-30 floor) ============
        const int wtid = tid - 128;     // 0..127
        for (int c = 0; c <= ct; ++c) {
            const int s = c & 3, u = c >> 2;
            mbar_wait(EMPTY_A(s), (u & 1) ^ 1);
            float* buf = sbuf + s * BUF_FLOATS;
            const float* gsrc = pbase + c * TC;
#pragma unroll
            for (int k = 0; k < 16; ++k) {
                const int i   = wtid + k * 128;    // 0..2047
                const int row = i >> 3;
                const int c4  = (i & 7) * 4;
                const float4 v = *reinterpret_cast<const float4*>(
                                     gsrc + (size_t)row * TT + c4);
                float* sp = buf + row * SROW + c4;
                sp[0] = v.x + 1e-30f; sp[1] = v.y + 1e-30f;
                sp[2] = v.z + 1e-30f; sp[3] = v.w + 1e-30f;
            }
            if (lane == 0) mbar_arrive(FULL_A(s));
        }
    } else if (warp < nact) {
        // ======================= recursion / consumer ======================
        const int Wb = 64 * warp - 32;
        const int r0 = Wb + 3 * lane, r1 = r0 + 1, r2 = r0 + 2;
        const int cr0 = ((r0 >= 0) ? r0 : 0) * SROW;   // invalid slots keep a=0
        const int cr1 = ((r1 >= 0) ? r1 : 0) * SROW;
        const int cr2 = ((r2 >= 0) ? r2 : 0) * SROW;
        const unsigned bar_n = (unsigned)(nact << 5);  // halo barrier threads

        const int wt   = tgt_l >> 6;
        const int slot = (tgt_l & 63) + 32;
        const bool mine = (warp == wt) && (lane == slot / 3);
        const int  msel = slot - 3 * (slot / 3);

        float a0 = 0.f, a1 = 0.f, a2 = 0.f;
        int   e0 = E_SENT, e1 = E_SENT, e2 = E_SENT;
        float f0 = 0.f, f1 = 0.f, f2 = 0.f;

#define SNAPVAL(AV, EV) ((AV) == 0.0f ? -1e30f : (f_lg2(AV) + (float)(EV)) * LN2)

#define STEP(BUFC, J, T)                                                  \
        {                                                                 \
            float p0 = (BUFC)[cr0 + (J)];                                 \
            float p1 = (BUFC)[cr1 + (J)];                                 \
            float p2 = (BUFC)[cr2 + (J)];                                 \
            float sh = __shfl_up_sync(0xffffffffu, a2, 1);                \
            float t0 = fmaf(sh, f0, a0);     /* lane0: f0==0 */           \
            float t1 = fmaf(a0, f1, a1);                                  \
            float t2 = fmaf(a1, f2, a2);                                  \
            a0 = t0 * p0; a1 = t1 * p1; a2 = t2 * p2;                     \
            if (mine && (T) == tgt_t) {                                   \
                float av = (msel == 0) ? a0 : ((msel == 1) ? a1 : a2);    \
                int   ev = (msel == 0) ? e0 : ((msel == 1) ? e1 : e2);    \
                g_alpha_last[b] = SNAPVAL(av, ev);                        \
            }                                                             \
        }

#define RENORM()                                                          \
        {                                                                 \
            int bi, ex;                                                   \
            bi = __float_as_int(a0); ex = (bi >> 23) & 255;               \
            bool R0 = (ex != 0);                                          \
            if (R0) { e0 += ex - 127;                                     \
                      a0 = __int_as_float((bi & 0x807FFFFF) | 0x3F800000);}\
            else    { a0 = 0.f; e0 = E_SENT; }                            \
            bi = __float_as_int(a1); ex = (bi >> 23) & 255;               \
            bool R1 = (ex != 0);                                          \
            if (R1) { e1 += ex - 127;                                     \
                      a1 = __int_as_float((bi & 0x807FFFFF) | 0x3F800000);}\
            else    { a1 = 0.f; e1 = E_SENT; }                            \
            bi = __float_as_int(a2); ex = (bi >> 23) & 255;               \
            bool R2 = (ex != 0);                                          \
            if (R2) { e2 += ex - 127;                                     \
                      a2 = __int_as_float((bi & 0x807FFFFF) | 0x3F800000);}\
            else    { a2 = 0.f; e2 = E_SENT; }                            \
            int lv = R2 ? e2 : (R1 ? e1 : (R0 ? e0 : E_SENT));            \
            int lf = (int)(R0 | R1 | R2);                                 \
            _Pragma("unroll")                                             \
            for (int d = 1; d < 8; d <<= 1) {                             \
                int ov = __shfl_up_sync(0xffffffffu, lv, d);              \
                int of = __shfl_up_sync(0xffffffffu, lf, d);              \
                if (lane >= d && !lf) { lv = ov; lf = of; }               \
            }                                                             \
            int Lin = __shfl_up_sync(0xffffffffu, lv, 1);                 \
            if (lane == 0) Lin = E_SENT;                                  \
            int pl = __shfl_up_sync(0xffffffffu, e2, 1);                  \
            if (lane == 0) pl = E_SENT;                                   \
            int P0 = R0 ? ((e0 > pl) ? e0 : pl) : Lin;                    \
            int L1 = R0 ? e0 : Lin;                                       \
            int P1 = R1 ? ((e1 > e0) ? e1 : e0) : L1;                     \
            int L2 = R1 ? e1 : L1;                                        \
            int P2 = R2 ? ((e2 > e1) ? e2 : e1) : L2;                     \
            a0 *= pow2s(e0 - P0);                                         \
            a1 *= pow2s(e1 - P1);                                         \
            a2 *= pow2s(e2 - P2);                                         \
            int PL = __shfl_up_sync(0xffffffffu, P2, 1);                  \
            if (lane == 0) PL = E_SENT;                                   \
            f0 = pow2s(PL - P0);                                          \
            if (lane == 0) f0 = 0.0f;   /* degradation front */           \
            f1 = pow2s(P0 - P1);                                          \
            f2 = pow2s(P1 - P2);                                          \
            e0 = P0; e1 = P1; e2 = P2;                                    \
        }

#define HALO(C)                                                           \
        {                                                                 \
            const int s0 = 3 * lane;                                      \
            float* ha = &hA[(C) & 1][warp][0];                            \
            int*   he = &hE[(C) & 1][warp][0];                            \
            if (s0     >= 64) { ha[s0 - 64] = a0; he[s0 - 64] = e0; }     \
            if (s0 + 1 >= 64) { ha[s0 - 63] = a1; he[s0 - 63] = e1; }     \
            if (s0 + 2 >= 64) { ha[s0 - 62] = a2; he[s0 - 62] = e2; }     \
            asm volatile("bar.sync 1, %0;" :: "r"(bar_n) : "memory");     \
            if (warp > 0) {                                               \
                const float* ra = &hA[(C) & 1][warp - 1][0];              \
                const int*   re = &hE[(C) & 1][warp - 1][0];              \
                if (s0     < 32) { a0 = ra[s0];     e0 = re[s0];     }    \
                if (s0 + 1 < 32) { a1 = ra[s0 + 1]; e1 = re[s0 + 1]; }    \
                if (s0 + 2 < 32) { a2 = ra[s0 + 2]; e2 = re[s0 + 2]; }    \
            }                                                             \
        }

        // ---- chunk 0 (t=0 is init, steps t=1..31) ----
        mbar_wait(FULL_A(0), 0);
        {
            const float* bufc = sbuf;
            if (warp == 0 && lane == 10) { a2 = bufc[0]; e2 = 0; }  // pre-floored
            if (tgt_t == 0 && mine) {
                float av = (msel == 0) ? a0 : ((msel == 1) ? a1 : a2);
                int   ev = (msel == 0) ? e0 : ((msel == 1) ? e1 : e2);
                g_alpha_last[b] = SNAPVAL(av, ev);
            }
            RENORM()
#pragma unroll
            for (int j = 1; j < 16; ++j) STEP(bufc, j, j)
            RENORM()
#pragma unroll
            for (int j = 16; j < 32; ++j) STEP(bufc, j, j)
        }
        if (lane == 0) mbar_arrive(EMPTY_A(0));
        HALO(0)

        // ---- chunks 1..ct ----
        for (int c = 1; c <= ct; ++c) {
            const int s = c & 3, u = c >> 2;
            mbar_wait(FULL_A(s), u & 1);
            const float* bufc = sbuf + s * BUF_FLOATS;
            const int tbase = c * TC;
            RENORM()
#pragma unroll
            for (int j = 0; j < 16; ++j) STEP(bufc, j, tbase + j)
            RENORM()
#pragma unroll
            for (int j = 16; j < 32; ++j) STEP(bufc, j, tbase + j)
            if (lane == 0) mbar_arrive(EMPTY_A(s));
            HALO(c)
        }
    }

    // ================ POST-PHASE: log output for chunks ct+1..49 ==========
    // All warps fall through as they finish their role (dead rec warps start
    // immediately). Thread-sliced; disjoint indices; no sync needed (regions
    // written here are read by nobody in this kernel).
    for (int c = ct + 1; c < NCH; ++c) {
        const float* gsrc = pbase + c * TC;
        float*       gdst = obase + c * TC;
#pragma unroll
        for (int k = 0; k < 6; ++k) {
            const int i = tid + k * 384;       // 0..2303, need < 2048
            if (i < 2048) {
                const int row = i >> 3;
                const int c4  = (i & 7) * 4;
                const float4 v = *reinterpret_cast<const float4*>(
                                     gsrc + (size_t)row * TT + c4);
                float* gp = gdst + (size_t)row * TT + c4;  // 4B-aligned
                gp[0] = __logf(v.x + 1e-30f);
                gp[1] = __logf(v.y + 1e-30f);
                gp[2] = __logf(v.z + 1e-30f);
                gp[3] = __logf(v.w + 1e-30f);
            }
        }
    }

    __syncthreads();

    // last block to finish computes loss = -mean(alpha_last)
    if (tid == 0) {
        __threadfence();
        unsigned old = atomicAdd(&g_done_ctr, 1u);
        if (old == BB - 1) {
            g_done_ctr = 0;                          // reset for graph replay
            __threadfence();
            float s = 0.0f;
#pragma unroll
            for (int i = 0; i < BB; ++i) s += g_alpha_last[i];
            out[0] = -s * (1.0f / BB);
        }
    }
}

// ---------------------------------------------------------------------------
extern "C" void kernel_launch(void* const* d_in, const int* in_sizes, int n_in,
                              void* d_out, int out_size)
{
    const float* probs        = (const float*)d_in[0];
    // d_in[1] = melspec (unused by the computation)
    const int*   text_lengths = (const int*)d_in[2];
    const int*   mel_lengths  = (const int*)d_in[3];

    float* out = (float*)d_out;   // out[0] = loss, out[1..] = log matrix

    static bool attr_set = false;
    if (!attr_set) {
        cudaFuncSetAttribute(k_rec, cudaFuncAttributeMaxDynamicSharedMemorySize,
                             SMEM_BYTES);
        attr_set = true;
    }

    k_rec<<<BB, 384, SMEM_BYTES, 0>>>(probs, text_lengths, mel_lengths, out);
    (void)in_sizes; (void)n_in; (void)out_size;
}